// round 4
// baseline (speedup 1.0000x reference)
#include <cuda_runtime.h>
#include <math.h>

// Problem constants
#define BATCH 8
#define LEN   4096
#define EMB   1024
#define HEADS 16
#define HD    64
#define M_TOT (BATCH*LEN)   // 32768

// ---------------------------------------------------------------------------
// Scratch (device globals; no allocation allowed)
// ---------------------------------------------------------------------------
__device__ float g_Q[(size_t)EMB * M_TOT];      // [o][m], m = b*4096 + l  (L contiguous)
__device__ float g_K[(size_t)EMB * M_TOT];
__device__ float g_attn[BATCH*HEADS*LEN];       // [bh][tau]
__device__ float g_zPart[8 * BATCH*HEADS * EMB];
__device__ float g_z[BATCH*HEADS*EMB];          // [bh][i]
__device__ float g_u[BATCH*EMB];                // [b][d*16+h]
__device__ float g_final[BATCH*EMB];            // [b][o]

// ---------------------------------------------------------------------------
// Kernel A: fp32 SGEMM, computes QT[o][m] = sum_i x[m,i]*W[o,i] (no bias).
// blockIdx.z: 0 -> (Wq, g_Q), 1 -> (Wk, g_K).
// 128x128 tile, BK=16, 256 threads, 8x8 per thread. Output stored transposed
// (o-major, m contiguous) so the FFT kernel reads channels coalesced.
// ---------------------------------------------------------------------------
__global__ void __launch_bounds__(256) proj_gemm(const float* __restrict__ X,
                                                 const float* __restrict__ Wq,
                                                 const float* __restrict__ Wk) {
    const float* W  = (blockIdx.z == 0) ? Wq : Wk;
    float* out      = (blockIdx.z == 0) ? g_Q : g_K;

    __shared__ float As[16][128];
    __shared__ float Bs[16][128];

    const int t  = threadIdx.x;
    const int tx = t & 15;        // o sub-tile
    const int ty = t >> 4;        // m sub-tile
    const int m0 = blockIdx.x * 128;
    const int n0 = blockIdx.y * 128;

    const int lr = t >> 2;          // 0..63
    const int lc = (t & 3) << 2;    // 0,4,8,12

    float acc[8][8];
#pragma unroll
    for (int i = 0; i < 8; i++)
#pragma unroll
        for (int j = 0; j < 8; j++) acc[i][j] = 0.f;

    for (int k0 = 0; k0 < EMB; k0 += 16) {
        float4 a0 = *(const float4*)&X[(size_t)(m0 + lr)      * EMB + k0 + lc];
        float4 a1 = *(const float4*)&X[(size_t)(m0 + lr + 64) * EMB + k0 + lc];
        float4 b0 = *(const float4*)&W[(size_t)(n0 + lr)      * EMB + k0 + lc];
        float4 b1 = *(const float4*)&W[(size_t)(n0 + lr + 64) * EMB + k0 + lc];
        __syncthreads();
        As[lc+0][lr] = a0.x; As[lc+1][lr] = a0.y; As[lc+2][lr] = a0.z; As[lc+3][lr] = a0.w;
        As[lc+0][lr+64] = a1.x; As[lc+1][lr+64] = a1.y; As[lc+2][lr+64] = a1.z; As[lc+3][lr+64] = a1.w;
        Bs[lc+0][lr] = b0.x; Bs[lc+1][lr] = b0.y; Bs[lc+2][lr] = b0.z; Bs[lc+3][lr] = b0.w;
        Bs[lc+0][lr+64] = b1.x; Bs[lc+1][lr+64] = b1.y; Bs[lc+2][lr+64] = b1.z; Bs[lc+3][lr+64] = b1.w;
        __syncthreads();
#pragma unroll
        for (int kk = 0; kk < 16; kk++) {
            float a[8], b[8];
            *(float4*)&a[0] = *(float4*)&As[kk][ty*8];
            *(float4*)&a[4] = *(float4*)&As[kk][ty*8+4];
            *(float4*)&b[0] = *(float4*)&Bs[kk][tx*8];
            *(float4*)&b[4] = *(float4*)&Bs[kk][tx*8+4];
#pragma unroll
            for (int i = 0; i < 8; i++)
#pragma unroll
                for (int j = 0; j < 8; j++) acc[i][j] += a[i]*b[j];
        }
    }

    // Write transposed: out[o][m], m contiguous per o.
#pragma unroll
    for (int j = 0; j < 8; j++) {
        int o = n0 + tx*8 + j;
        float* dst = &out[(size_t)o * M_TOT + m0 + ty*8];
        float4 v0 = make_float4(acc[0][j], acc[1][j], acc[2][j], acc[3][j]);
        float4 v1 = make_float4(acc[4][j], acc[5][j], acc[6][j], acc[7][j]);
        *(float4*)&dst[0] = v0;
        *(float4*)&dst[4] = v1;
    }
}

// ---------------------------------------------------------------------------
// In-place 4096-point complex FFT (DIF radix-4 + digit-reverse), 512 threads.
// Natural order in -> natural order out. Forward transform (W = e^{-2pi i/N}).
// ---------------------------------------------------------------------------
__device__ __forceinline__ void fft4096(float* zr, float* zi,
                                        const float* twr, const float* twi) {
    const int tid = threadIdx.x;
#pragma unroll
    for (int n = 4096; n >= 4; n >>= 2) {
        const int q    = n >> 2;
        const int step = 4096 / n;
        __syncthreads();
#pragma unroll
        for (int t = tid; t < 1024; t += 512) {
            const int blk  = t / q;
            const int j    = t - blk * q;
            const int base = blk * n + j;
            float ar = zr[base],       ai = zi[base];
            float br = zr[base+q],     bi = zi[base+q];
            float cr = zr[base+2*q],   ci = zi[base+2*q];
            float dr = zr[base+3*q],   di = zi[base+3*q];
            float t0r = ar+cr, t0i = ai+ci;
            float t1r = ar-cr, t1i = ai-ci;
            float t2r = br+dr, t2i = bi+di;
            float t3r = br-dr, t3i = bi-di;
            float y0r = t0r+t2r, y0i = t0i+t2i;
            float y2r = t0r-t2r, y2i = t0i-t2i;
            float y1r = t1r+t3i, y1i = t1i-t3r;   // t1 - i*t3
            float y3r = t1r-t3i, y3i = t1i+t3r;   // t1 + i*t3
            int i1 = j*step, i2 = (2*j*step) & 4095, i3 = (3*j*step) & 4095;
            float w1r = twr[i1], w1i = twi[i1];
            float w2r = twr[i2], w2i = twi[i2];
            float w3r = twr[i3], w3i = twi[i3];
            zr[base]     = y0r;                 zi[base]     = y0i;
            zr[base+q]   = y1r*w1r - y1i*w1i;   zi[base+q]   = y1r*w1i + y1i*w1r;
            zr[base+2*q] = y2r*w2r - y2i*w2i;   zi[base+2*q] = y2r*w2i + y2i*w2r;
            zr[base+3*q] = y3r*w3r - y3i*w3i;   zi[base+3*q] = y3r*w3i + y3i*w3r;
        }
    }
    __syncthreads();
    // base-4 digit-reverse permutation (involution -> disjoint pair swaps)
    for (int idx = tid; idx < 4096; idx += 512) {
        int r = 0, v = idx;
#pragma unroll
        for (int s = 0; s < 6; s++) { r = (r << 2) | (v & 3); v >>= 2; }
        if (r > idx) {
            float tr = zr[idx]; zr[idx] = zr[r]; zr[r] = tr;
            float ti = zi[idx]; zi[idx] = zi[r]; zi[r] = ti;
        }
    }
    __syncthreads();
}

// ---------------------------------------------------------------------------
// Kernel B: one CTA per (b,h). For each d: FFT(q + i*k) via two-for-one,
// accumulate S[f] += Qf*conj(Kf) in registers. Then corr = Re(IFFT(S))/(N*D),
// softmax over tau, write attn.
// dyn smem: zr[4096], zi[4096], twr[4096], twi[4096], red[512]  = 66.5 KB
// ---------------------------------------------------------------------------
__global__ void __launch_bounds__(512) corr_softmax_kernel() {
    extern __shared__ float sm[];
    float* zr  = sm;
    float* zi  = sm + 4096;
    float* twr = sm + 8192;
    float* twi = sm + 12288;
    float* red = sm + 16384;

    const int tid = threadIdx.x;
    const int b = blockIdx.x >> 4, h = blockIdx.x & 15;

    // twiddle table W^j = exp(-2*pi*i*j/4096)
    for (int j = tid; j < 4096; j += 512) {
        float s, c;
        sincosf(-6.283185307179586f * (float)j / 4096.0f, &s, &c);
        twr[j] = c; twi[j] = s;
    }

    float sre[8], smi[8];
#pragma unroll
    for (int k = 0; k < 8; k++) { sre[k] = 0.f; smi[k] = 0.f; }

    for (int d = 0; d < HD; d++) {
        const int o = h*HD + d;
        const float* qp = &g_Q[(size_t)o * M_TOT + b*LEN];
        const float* kp = &g_K[(size_t)o * M_TOT + b*LEN];
        __syncthreads();   // protect prior extraction reads
        for (int l = tid; l < 4096; l += 512) { zr[l] = qp[l]; zi[l] = kp[l]; }
        fft4096(zr, zi, twr, twi);
        // extract Qf, Kf from Z = Qf + i*Kf; accumulate S += Qf*conj(Kf)
#pragma unroll
        for (int k = 0; k < 8; k++) {
            int f  = tid + (k << 9);
            int fm = (4096 - f) & 4095;
            float ar = zr[f], ai = zi[f], pr = zr[fm], pi = zi[fm];
            float qr = 0.5f*(ar + pr), qi = 0.5f*(ai - pi);
            float kr = 0.5f*(ai + pi), ki = 0.5f*(pr - ar);
            sre[k] += qr*kr + qi*ki;
            smi[k] += qi*kr - qr*ki;
        }
    }

    __syncthreads();
    // IFFT(S) = conj(FFT(conj(S)))/N; we only need the real part.
#pragma unroll
    for (int k = 0; k < 8; k++) {
        int f = tid + (k << 9);
        zr[f] = sre[k]; zi[f] = -smi[k];
    }
    fft4096(zr, zi, twr, twi);

    const float inv = 1.0f / (4096.0f * 64.0f);   // 1/N (irfft) * 1/D (mean)

    // softmax over zr[0..4095]*inv
    float lm = -1e30f;
    for (int t = tid; t < 4096; t += 512) lm = fmaxf(lm, zr[t]);
    red[tid] = lm; __syncthreads();
    for (int s = 256; s > 0; s >>= 1) {
        if (tid < s) red[tid] = fmaxf(red[tid], red[tid+s]);
        __syncthreads();
    }
    const float mx = red[0] * inv;
    __syncthreads();

    float ls = 0.f;
    for (int t = tid; t < 4096; t += 512) {
        float e = __expf(zr[t]*inv - mx);
        zi[t] = e;           // zi reused as exp storage
        ls += e;
    }
    red[tid] = ls; __syncthreads();
    for (int s = 256; s > 0; s >>= 1) {
        if (tid < s) red[tid] += red[tid+s];
        __syncthreads();
    }
    const float rden = 1.0f / red[0];

    float* ap = &g_attn[blockIdx.x * LEN];
    for (int t = tid; t < 4096; t += 512) ap[t] = zi[t] * rden;
}

// ---------------------------------------------------------------------------
// Kernel C: zPart[ts][b*16+h][i] = sum_{tau in ts-slice} attn[b,h,tau]*x[b,tau,i]
// grid (ichunk=8, b=8, tsplit=8), 128 threads. Each thread: 1 i, 16 h-accs.
// ---------------------------------------------------------------------------
__global__ void __launch_bounds__(128) attnx_kernel(const float* __restrict__ x) {
    __shared__ float a_s[16][64];
    const int tid = threadIdx.x;
    const int ic = blockIdx.x, b = blockIdx.y, ts = blockIdx.z;
    const int i = ic * 128 + tid;

    float acc[16];
#pragma unroll
    for (int hh = 0; hh < 16; hh++) acc[hh] = 0.f;

    for (int t0 = ts*512; t0 < ts*512 + 512; t0 += 64) {
        __syncthreads();
#pragma unroll
        for (int r = 0; r < 8; r++) {
            int e  = r*128 + tid;
            int hh = e >> 6, tt = e & 63;
            a_s[hh][tt] = g_attn[((b*16 + hh) << 12) + t0 + tt];
        }
        __syncthreads();
#pragma unroll 4
        for (int tt = 0; tt < 64; tt++) {
            float xv = x[(size_t)(b*LEN + t0 + tt) * EMB + i];
#pragma unroll
            for (int hh = 0; hh < 16; hh++) acc[hh] += a_s[hh][tt] * xv;
        }
    }
#pragma unroll
    for (int hh = 0; hh < 16; hh++)
        g_zPart[(ts*128 + b*16 + hh) * EMB + i] = acc[hh];
}

__global__ void zreduce_kernel() {
    int idx = blockIdx.x * blockDim.x + threadIdx.x;   // 131072 total
    float s = 0.f;
#pragma unroll
    for (int ts = 0; ts < 8; ts++) s += g_zPart[ts * (BATCH*HEADS*EMB) + idx];
    g_z[idx] = s;
}

// ---------------------------------------------------------------------------
// Kernel D1: u[b, d*16+h] = Wv[h*64+d,:] . z[b*16+h,:] + bv[h*64+d]
// one warp per output
// ---------------------------------------------------------------------------
__global__ void __launch_bounds__(256) uproj_kernel(const float* __restrict__ Wv,
                                                    const float* __restrict__ bv) {
    const int w    = (blockIdx.x * 256 + threadIdx.x) >> 5;  // 0..8191
    const int lane = threadIdx.x & 31;
    const int b = w >> 10, e = w & 1023;
    const int d = e >> 4, hh = e & 15;
    const int ov = hh*HD + d;
    const float* wrow = &Wv[(size_t)ov * EMB];
    const float* zrow = &g_z[(b*16 + hh) * EMB];
    float s = 0.f;
    for (int i = lane; i < EMB; i += 32) s += wrow[i] * zrow[i];
#pragma unroll
    for (int off = 16; off; off >>= 1) s += __shfl_down_sync(0xffffffffu, s, off);
    if (lane == 0) g_u[b*EMB + e] = s + bv[ov];
}

// Kernel D2: final[b,o] = u[b,:] . Wo[o,:] + bo[o]
__global__ void __launch_bounds__(256) oproj_kernel(const float* __restrict__ Wo,
                                                    const float* __restrict__ bo) {
    const int w    = (blockIdx.x * 256 + threadIdx.x) >> 5;
    const int lane = threadIdx.x & 31;
    const int b = w >> 10, o = w & 1023;
    const float* wrow = &Wo[(size_t)o * EMB];
    const float* urow = &g_u[b*EMB];
    float s = 0.f;
    for (int i = lane; i < EMB; i += 32) s += wrow[i] * urow[i];
#pragma unroll
    for (int off = 16; off; off >>= 1) s += __shfl_down_sync(0xffffffffu, s, off);
    if (lane == 0) g_final[b*EMB + o] = s + bo[o];
}

// Kernel E: broadcast final[b,:] over all L rows of the output.
__global__ void __launch_bounds__(256) bcast_kernel(float4* __restrict__ out) {
    const int idx = blockIdx.x * 256 + threadIdx.x;   // < 8388608
    const int b  = idx >> 20;                         // 4096*256 f4 per batch
    const int o4 = idx & 255;
    out[idx] = *(const float4*)&g_final[(b << 10) + (o4 << 2)];
}

// ---------------------------------------------------------------------------
extern "C" void kernel_launch(void* const* d_in, const int* in_sizes, int n_in,
                              void* d_out, int out_size) {
    const float* x  = (const float*)d_in[0];
    const float* Wq = (const float*)d_in[1];
    // d_in[2] = bq  (provably irrelevant through circular corr + softmax)
    const float* Wk = (const float*)d_in[3];
    // d_in[4] = bk  (irrelevant, same argument)
    const float* Wv = (const float*)d_in[5];
    const float* bv = (const float*)d_in[6];
    const float* Wo = (const float*)d_in[7];
    const float* bo = (const float*)d_in[8];

    const int smemB = (4*4096 + 512) * (int)sizeof(float);   // 66.5 KB
    cudaFuncSetAttribute(corr_softmax_kernel,
                         cudaFuncAttributeMaxDynamicSharedMemorySize, smemB);

    proj_gemm<<<dim3(M_TOT/128, EMB/128, 2), 256>>>(x, Wq, Wk);
    corr_softmax_kernel<<<BATCH*HEADS, 512, smemB>>>();
    attnx_kernel<<<dim3(8, 8, 8), 128>>>(x);
    zreduce_kernel<<<512, 256>>>();
    uproj_kernel<<<1024, 256>>>(Wv, bv);
    oproj_kernel<<<1024, 256>>>(Wo, bo);
    bcast_kernel<<<(BATCH*LEN*EMB/4)/256, 256>>>((float4*)d_out);
}

// round 12
// speedup vs baseline: 1.8958x; 1.8958x over previous
#include <cuda_runtime.h>
#include <cuda_bf16.h>
#include <math.h>
#include <stdint.h>

// Problem constants
#define BATCH 8
#define LEN   4096
#define EMB   1024
#define HEADS 16
#define HD    64
#define M_TOT (BATCH*LEN)   // 32768

#define OTILES 8            // 1024/128
#define MTILES 256          // 32768/128
#define NCHUNK 32           // 1024/32  (BK=32)
#define LDS    40           // smem row stride (bf16 elems), pad vs 32

// ---------------------------------------------------------------------------
// Scratch (device globals; no allocation allowed)
// ---------------------------------------------------------------------------
__device__ float g_Q[(size_t)EMB * M_TOT];      // [o][m], m = b*4096 + l
__device__ float g_K[(size_t)EMB * M_TOT];
__device__ float g_attn[BATCH*HEADS*LEN];
__device__ float g_zPart[8 * BATCH*HEADS * EMB];
__device__ float g_z[BATCH*HEADS*EMB];
__device__ float g_u[BATCH*EMB];
__device__ float g_final[BATCH*EMB];

// Pre-split bf16 hi/lo images, plain row-major (K contiguous).
__device__ __nv_bfloat16 g_Xh[(size_t)M_TOT * EMB];
__device__ __nv_bfloat16 g_Xl[(size_t)M_TOT * EMB];
__device__ __nv_bfloat16 g_Wqh[(size_t)EMB * EMB];
__device__ __nv_bfloat16 g_Wql[(size_t)EMB * EMB];
__device__ __nv_bfloat16 g_Wkh[(size_t)EMB * EMB];
__device__ __nv_bfloat16 g_Wkl[(size_t)EMB * EMB];

// ---------------------------------------------------------------------------
// Helpers
// ---------------------------------------------------------------------------
__device__ __forceinline__ uint32_t smem_u32(const void* p) {
    uint32_t a;
    asm("{ .reg .u64 t; cvta.to.shared.u64 t, %1; cvt.u32.u64 %0, t; }" : "=r"(a) : "l"(p));
    return a;
}
__device__ __forceinline__ void ldsm4(uint32_t* r, uint32_t addr) {
    asm volatile("ldmatrix.sync.aligned.m8n8.x4.shared.b16 {%0,%1,%2,%3}, [%4];"
                 : "=r"(r[0]), "=r"(r[1]), "=r"(r[2]), "=r"(r[3]) : "r"(addr));
}
__device__ __forceinline__ void mma_bf16(float* c, const uint32_t* a, const uint32_t* b) {
    asm volatile(
        "mma.sync.aligned.m16n8k16.row.col.f32.bf16.bf16.f32 "
        "{%0,%1,%2,%3}, {%4,%5,%6,%7}, {%8,%9}, {%0,%1,%2,%3};"
        : "+f"(c[0]), "+f"(c[1]), "+f"(c[2]), "+f"(c[3])
        : "r"(a[0]), "r"(a[1]), "r"(a[2]), "r"(a[3]), "r"(b[0]), "r"(b[1]));
}
__device__ __forceinline__ void split4(const float4 v, uint2* hu, uint2* lu) {
    __nv_bfloat162 h0 = __floats2bfloat162_rn(v.x, v.y);   // low=x, high=y
    __nv_bfloat162 h1 = __floats2bfloat162_rn(v.z, v.w);
    float rx = v.x - __low2float(h0),  ry = v.y - __high2float(h0);
    float rz = v.z - __low2float(h1),  rw = v.w - __high2float(h1);
    __nv_bfloat162 l0 = __floats2bfloat162_rn(rx, ry);
    __nv_bfloat162 l1 = __floats2bfloat162_rn(rz, rw);
    *hu = make_uint2(*reinterpret_cast<uint32_t*>(&h0), *reinterpret_cast<uint32_t*>(&h1));
    *lu = make_uint2(*reinterpret_cast<uint32_t*>(&l0), *reinterpret_cast<uint32_t*>(&l1));
}

// ---------------------------------------------------------------------------
// Pre-split: fp32 -> (bf16 hi, bf16 lo), plain layout, fully coalesced.
// ---------------------------------------------------------------------------
__global__ void __launch_bounds__(256) presplit_x(const float* __restrict__ X) {
    size_t idx = (size_t)blockIdx.x * 256 + threadIdx.x;   // float4 index
    float4 v = ((const float4*)X)[idx];
    uint2 hu, lu;
    split4(v, &hu, &lu);
    ((uint2*)g_Xh)[idx] = hu;
    ((uint2*)g_Xl)[idx] = lu;
}

__global__ void __launch_bounds__(256) presplit_w(const float* __restrict__ Wq,
                                                  const float* __restrict__ Wk) {
    size_t idx = (size_t)blockIdx.x * 256 + threadIdx.x;
    uint2 hu, lu;
    split4(((const float4*)Wq)[idx], &hu, &lu);
    ((uint2*)g_Wqh)[idx] = hu;
    ((uint2*)g_Wql)[idx] = lu;
    split4(((const float4*)Wk)[idx], &hu, &lu);
    ((uint2*)g_Wkh)[idx] = hu;
    ((uint2*)g_Wkl)[idx] = lu;
}

// ---------------------------------------------------------------------------
// Kernel A: bf16 2-term-split GEMM via mma.sync (HMMA path; sm_103 base ISA).
// D[o][m] = sum_k W[o][k] * X[m][k]   (hh + hl + lh in fp32 accumulators)
// CTA tile 128(o) x 128(m), BK=32. 8 warps = 2(o) x 4(m); warp tile 64x32.
// grid (8, 256, 2): z=0 -> Wq->g_Q, z=1 -> Wk->g_K.
// ---------------------------------------------------------------------------
__global__ void __launch_bounds__(256) qk_mma() {
    __shared__ __nv_bfloat16 sAh[128*LDS], sAl[128*LDS];
    __shared__ __nv_bfloat16 sBh[128*LDS], sBl[128*LDS];

    const int tid  = threadIdx.x;
    const int wid  = tid >> 5;
    const int lane = tid & 31;
    const int o0 = blockIdx.x * 128;
    const int m0 = blockIdx.y * 128;
    const int z  = blockIdx.z;

    const __nv_bfloat16* Ah = z ? g_Wkh : g_Wqh;
    const __nv_bfloat16* Al = z ? g_Wkl : g_Wql;
    float* OUT = z ? g_K : g_Q;

    const int warp_o = wid & 1;            // 0,1  -> o offset 0/64
    const int warp_m = wid >> 1;           // 0..3 -> m offset 0/32/64/96

    const uint32_t uAh = smem_u32(sAh), uAl = smem_u32(sAl);
    const uint32_t uBh = smem_u32(sBh), uBl = smem_u32(sBl);

    float acc[4][4][4];
#pragma unroll
    for (int i = 0; i < 4; i++)
#pragma unroll
        for (int j = 0; j < 4; j++)
#pragma unroll
            for (int r = 0; r < 4; r++) acc[i][j][r] = 0.f;

    // ldmatrix address offsets (elements) computed once per thread
    const int a_row = (lane & 15);               // + i*16 + warp_o*64
    const int a_kof = (lane >> 4) * 8;           // + s*16
    const int b_row = ((lane >> 4) & 1) * 8 + (lane & 7);   // + p*16 + warp_m*32
    const int b_kof = ((lane >> 3) & 1) * 8;                 // + s*16

    for (int c = 0; c < NCHUNK; c++) {
        const int k0 = c * 32;
        __syncthreads();   // protect prior ldmatrix reads
        // load 4 tiles: 128 rows x 32 cols each; 512 16B-loads per tile
#pragma unroll
        for (int it = 0; it < 2; it++) {
            const int i   = tid + it * 256;
            const int row = i >> 2;
            const int seg = (i & 3) * 8;
            const size_t gA = (size_t)(o0 + row) * EMB + k0 + seg;
            const size_t gB = (size_t)(m0 + row) * EMB + k0 + seg;
            const int so = row * LDS + seg;
            *(uint4*)&sAh[so] = *(const uint4*)&Ah[gA];
            *(uint4*)&sAl[so] = *(const uint4*)&Al[gA];
            *(uint4*)&sBh[so] = *(const uint4*)&g_Xh[gB];
            *(uint4*)&sBl[so] = *(const uint4*)&g_Xl[gB];
        }
        __syncthreads();

#pragma unroll
        for (int s = 0; s < 2; s++) {
            const int ks = s * 16;
            uint32_t ah[4][4], al[4][4];
#pragma unroll
            for (int i = 0; i < 4; i++) {
                const int r  = warp_o * 64 + i * 16 + a_row;
                const uint32_t off = (uint32_t)(r * LDS + ks + a_kof) * 2;
                ldsm4(ah[i], uAh + off);
                ldsm4(al[i], uAl + off);
            }
            uint32_t bh[4][2], bl[4][2];
#pragma unroll
            for (int p = 0; p < 2; p++) {
                const int r  = warp_m * 32 + p * 16 + b_row;
                const uint32_t off = (uint32_t)(r * LDS + ks + b_kof) * 2;
                uint32_t t[4];
                ldsm4(t, uBh + off);
                bh[2*p][0] = t[0]; bh[2*p][1] = t[1];
                bh[2*p+1][0] = t[2]; bh[2*p+1][1] = t[3];
                ldsm4(t, uBl + off);
                bl[2*p][0] = t[0]; bl[2*p][1] = t[1];
                bl[2*p+1][0] = t[2]; bl[2*p+1][1] = t[3];
            }
#pragma unroll
            for (int i = 0; i < 4; i++)
#pragma unroll
                for (int j = 0; j < 4; j++) {
                    mma_bf16(acc[i][j], ah[i], bh[j]);   // hh
                    mma_bf16(acc[i][j], ah[i], bl[j]);   // hl
                    mma_bf16(acc[i][j], al[i], bh[j]);   // lh
                }
        }
    }

    // Epilogue: D frag mapping: row = lane>>2 (+8 for regs 2,3), col = (lane&3)*2
#pragma unroll
    for (int i = 0; i < 4; i++) {
        const int o_r = o0 + warp_o * 64 + i * 16 + (lane >> 2);
#pragma unroll
        for (int j = 0; j < 4; j++) {
            const int m_c = m0 + warp_m * 32 + j * 8 + (lane & 3) * 2;
            *(float2*)&OUT[(size_t)o_r * M_TOT + m_c]       = make_float2(acc[i][j][0], acc[i][j][1]);
            *(float2*)&OUT[(size_t)(o_r + 8) * M_TOT + m_c] = make_float2(acc[i][j][2], acc[i][j][3]);
        }
    }
}

// ---------------------------------------------------------------------------
// 4096-pt complex FFT (radix-4 DIF + digit-reverse), 512 threads, in smem.
// ---------------------------------------------------------------------------
__device__ __forceinline__ void fft4096(float* zr, float* zi,
                                        const float* twr, const float* twi) {
    const int tid = threadIdx.x;
#pragma unroll
    for (int n = 4096; n >= 4; n >>= 2) {
        const int q    = n >> 2;
        const int step = 4096 / n;
        __syncthreads();
#pragma unroll
        for (int t = tid; t < 1024; t += 512) {
            const int blk  = t / q;
            const int j    = t - blk * q;
            const int base = blk * n + j;
            float ar = zr[base],       ai = zi[base];
            float br = zr[base+q],     bi = zi[base+q];
            float cr = zr[base+2*q],   ci = zi[base+2*q];
            float dr = zr[base+3*q],   di = zi[base+3*q];
            float t0r = ar+cr, t0i = ai+ci;
            float t1r = ar-cr, t1i = ai-ci;
            float t2r = br+dr, t2i = bi+di;
            float t3r = br-dr, t3i = bi-di;
            float y0r = t0r+t2r, y0i = t0i+t2i;
            float y2r = t0r-t2r, y2i = t0i-t2i;
            float y1r = t1r+t3i, y1i = t1i-t3r;
            float y3r = t1r-t3i, y3i = t1i+t3r;
            int i1 = j*step, i2 = (2*j*step) & 4095, i3 = (3*j*step) & 4095;
            float w1r = twr[i1], w1i = twi[i1];
            float w2r = twr[i2], w2i = twi[i2];
            float w3r = twr[i3], w3i = twi[i3];
            zr[base]     = y0r;                 zi[base]     = y0i;
            zr[base+q]   = y1r*w1r - y1i*w1i;   zi[base+q]   = y1r*w1i + y1i*w1r;
            zr[base+2*q] = y2r*w2r - y2i*w2i;   zi[base+2*q] = y2r*w2i + y2i*w2r;
            zr[base+3*q] = y3r*w3r - y3i*w3i;   zi[base+3*q] = y3r*w3i + y3i*w3r;
        }
    }
    __syncthreads();
    for (int idx = tid; idx < 4096; idx += 512) {
        int r = 0, v = idx;
#pragma unroll
        for (int s = 0; s < 6; s++) { r = (r << 2) | (v & 3); v >>= 2; }
        if (r > idx) {
            float tr = zr[idx]; zr[idx] = zr[r]; zr[r] = tr;
            float ti = zi[idx]; zi[idx] = zi[r]; zi[r] = ti;
        }
    }
    __syncthreads();
}

// ---------------------------------------------------------------------------
// Kernel B: per (b,h): FFT two-for-one, S += Qf*conj(Kf), IFFT, softmax.
// ---------------------------------------------------------------------------
__global__ void __launch_bounds__(512) corr_softmax_kernel() {
    extern __shared__ float smf[];
    float* zr  = smf;
    float* zi  = smf + 4096;
    float* twr = smf + 8192;
    float* twi = smf + 12288;
    float* red = smf + 16384;

    const int tid = threadIdx.x;
    const int b = blockIdx.x >> 4, h = blockIdx.x & 15;

    for (int j = tid; j < 4096; j += 512) {
        float s, c;
        sincosf(-6.283185307179586f * (float)j / 4096.0f, &s, &c);
        twr[j] = c; twi[j] = s;
    }

    float sre[8], smi[8];
#pragma unroll
    for (int k = 0; k < 8; k++) { sre[k] = 0.f; smi[k] = 0.f; }

    for (int d = 0; d < HD; d++) {
        const int o = h*HD + d;
        const float* qp = &g_Q[(size_t)o * M_TOT + b*LEN];
        const float* kp = &g_K[(size_t)o * M_TOT + b*LEN];
        __syncthreads();
        for (int l = tid; l < 4096; l += 512) { zr[l] = qp[l]; zi[l] = kp[l]; }
        fft4096(zr, zi, twr, twi);
#pragma unroll
        for (int k = 0; k < 8; k++) {
            int f  = tid + (k << 9);
            int fm = (4096 - f) & 4095;
            float ar = zr[f], ai = zi[f], pr = zr[fm], pi = zi[fm];
            float qr = 0.5f*(ar + pr), qi = 0.5f*(ai - pi);
            float kr = 0.5f*(ai + pi), ki = 0.5f*(pr - ar);
            sre[k] += qr*kr + qi*ki;
            smi[k] += qi*kr - qr*ki;
        }
    }

    __syncthreads();
#pragma unroll
    for (int k = 0; k < 8; k++) {
        int f = tid + (k << 9);
        zr[f] = sre[k]; zi[f] = -smi[k];
    }
    fft4096(zr, zi, twr, twi);

    const float inv = 1.0f / (4096.0f * 64.0f);

    float lm = -1e30f;
    for (int t = tid; t < 4096; t += 512) lm = fmaxf(lm, zr[t]);
    red[tid] = lm; __syncthreads();
    for (int s = 256; s > 0; s >>= 1) {
        if (tid < s) red[tid] = fmaxf(red[tid], red[tid+s]);
        __syncthreads();
    }
    const float mx = red[0] * inv;
    __syncthreads();

    float ls = 0.f;
    for (int t = tid; t < 4096; t += 512) {
        float e = __expf(zr[t]*inv - mx);
        zi[t] = e;
        ls += e;
    }
    red[tid] = ls; __syncthreads();
    for (int s = 256; s > 0; s >>= 1) {
        if (tid < s) red[tid] += red[tid+s];
        __syncthreads();
    }
    const float rden = 1.0f / red[0];

    float* ap = &g_attn[blockIdx.x * LEN];
    for (int t = tid; t < 4096; t += 512) ap[t] = zi[t] * rden;
}

// ---------------------------------------------------------------------------
// Kernel C: zPart = attn @ x (tau-sliced partial sums), then reduce.
// ---------------------------------------------------------------------------
__global__ void __launch_bounds__(128) attnx_kernel(const float* __restrict__ x) {
    __shared__ float a_s[16][64];
    const int tid = threadIdx.x;
    const int ic = blockIdx.x, b = blockIdx.y, ts = blockIdx.z;
    const int i = ic * 128 + tid;

    float acc[16];
#pragma unroll
    for (int hh = 0; hh < 16; hh++) acc[hh] = 0.f;

    for (int t0 = ts*512; t0 < ts*512 + 512; t0 += 64) {
        __syncthreads();
#pragma unroll
        for (int r = 0; r < 8; r++) {
            int e  = r*128 + tid;
            int hh = e >> 6, tt = e & 63;
            a_s[hh][tt] = g_attn[((b*16 + hh) << 12) + t0 + tt];
        }
        __syncthreads();
#pragma unroll 4
        for (int tt = 0; tt < 64; tt++) {
            float xv = x[(size_t)(b*LEN + t0 + tt) * EMB + i];
#pragma unroll
            for (int hh = 0; hh < 16; hh++) acc[hh] += a_s[hh][tt] * xv;
        }
    }
#pragma unroll
    for (int hh = 0; hh < 16; hh++)
        g_zPart[(ts*128 + b*16 + hh) * EMB + i] = acc[hh];
}

__global__ void zreduce_kernel() {
    int idx = blockIdx.x * blockDim.x + threadIdx.x;
    float s = 0.f;
#pragma unroll
    for (int ts = 0; ts < 8; ts++) s += g_zPart[ts * (BATCH*HEADS*EMB) + idx];
    g_z[idx] = s;
}

// ---------------------------------------------------------------------------
// Small projections + broadcast
// ---------------------------------------------------------------------------
__global__ void __launch_bounds__(256) uproj_kernel(const float* __restrict__ Wv,
                                                    const float* __restrict__ bv) {
    const int w    = (blockIdx.x * 256 + threadIdx.x) >> 5;
    const int lane = threadIdx.x & 31;
    const int b = w >> 10, e = w & 1023;
    const int d = e >> 4, hh = e & 15;
    const int ov = hh*HD + d;
    const float* wrow = &Wv[(size_t)ov * EMB];
    const float* zrow = &g_z[(b*16 + hh) * EMB];
    float s = 0.f;
    for (int i = lane; i < EMB; i += 32) s += wrow[i] * zrow[i];
#pragma unroll
    for (int off = 16; off; off >>= 1) s += __shfl_down_sync(0xffffffffu, s, off);
    if (lane == 0) g_u[b*EMB + e] = s + bv[ov];
}

__global__ void __launch_bounds__(256) oproj_kernel(const float* __restrict__ Wo,
                                                    const float* __restrict__ bo) {
    const int w    = (blockIdx.x * 256 + threadIdx.x) >> 5;
    const int lane = threadIdx.x & 31;
    const int b = w >> 10, o = w & 1023;
    const float* wrow = &Wo[(size_t)o * EMB];
    const float* urow = &g_u[b*EMB];
    float s = 0.f;
    for (int i = lane; i < EMB; i += 32) s += wrow[i] * urow[i];
#pragma unroll
    for (int off = 16; off; off >>= 1) s += __shfl_down_sync(0xffffffffu, s, off);
    if (lane == 0) g_final[b*EMB + o] = s + bo[o];
}

__global__ void __launch_bounds__(256) bcast_kernel(float4* __restrict__ out) {
    const int idx = blockIdx.x * 256 + threadIdx.x;
    const int b  = idx >> 20;
    const int o4 = idx & 255;
    out[idx] = *(const float4*)&g_final[(b << 10) + (o4 << 2)];
}

// ---------------------------------------------------------------------------
extern "C" void kernel_launch(void* const* d_in, const int* in_sizes, int n_in,
                              void* d_out, int out_size) {
    const float* x  = (const float*)d_in[0];
    const float* Wq = (const float*)d_in[1];
    // d_in[2] = bq (irrelevant through circular corr + softmax)
    const float* Wk = (const float*)d_in[3];
    // d_in[4] = bk (irrelevant, same argument)
    const float* Wv = (const float*)d_in[5];
    const float* bv = (const float*)d_in[6];
    const float* Wo = (const float*)d_in[7];
    const float* bo = (const float*)d_in[8];

    const int smemB = (4*4096 + 512) * (int)sizeof(float);   // 66.5 KB
    cudaFuncSetAttribute(corr_softmax_kernel,
                         cudaFuncAttributeMaxDynamicSharedMemorySize, smemB);

    presplit_x<<<(int)((size_t)M_TOT*EMB/4/256), 256>>>(x);
    presplit_w<<<(int)((size_t)EMB*EMB/4/256), 256>>>(Wq, Wk);
    qk_mma<<<dim3(OTILES, MTILES, 2), 256>>>();
    corr_softmax_kernel<<<BATCH*HEADS, 512, smemB>>>();
    attnx_kernel<<<dim3(8, 8, 8), 128>>>(x);
    zreduce_kernel<<<512, 256>>>();
    uproj_kernel<<<1024, 256>>>(Wv, bv);
    oproj_kernel<<<1024, 256>>>(Wo, bo);
    bcast_kernel<<<(BATCH*LEN*EMB/4)/256, 256>>>((float4*)d_out);
}